// round 12
// baseline (speedup 1.0000x reference)
#include <cuda_runtime.h>
#include <math.h>
#include <stdint.h>

#define BS 16
#define TT 20
#define NN 512
#define EE 64
#define LL 8
#define STEPS 12
#define NROWS 19   // rows of skill_seq used as S-row indices (0..18)

// ---------------- scratch (device globals; no allocation allowed) ----------
__device__ float g_S[BS * 2 * NROWS * NN];   // S[b][k][r][n] = adj[k,b,sh_r,n] + adj2[k,b,sh_r,n]
__device__ float g_hA[BS * NN * EE];
__device__ float g_hB[BS * NN * EE];
__device__ float g_ew[STEPS * BS * LL];      // exp(-dtw)

// ---------------- helpers --------------------------------------------------
// HW tanh: single MUFU op (measured rel_err 1.6e-6 end-to-end)
__device__ __forceinline__ float tanha(float x) {
    float r;
    asm("tanh.approx.f32 %0, %1;" : "=f"(r) : "f"(x));
    return r;
}

__device__ __forceinline__ float warp_sum(float v) {
#pragma unroll
    for (int o = 16; o > 0; o >>= 1) v += __shfl_xor_sync(0xffffffffu, v, o);
    return v;
}

// packed f32x2 FMA: d = a*b + d
__device__ __forceinline__ void fma2(unsigned long long& d,
                                     unsigned long long a,
                                     unsigned long long b) {
    asm("fma.rn.f32x2 %0, %1, %2, %0;" : "+l"(d) : "l"(a), "l"(b));
}
__device__ __forceinline__ float red2(unsigned long long p) {
    float2 r;
    asm("mov.b64 {%0,%1}, %2;" : "=f"(r.x), "=f"(r.y) : "l"(p));
    return r.x + r.y;
}

// ---------------- hidden0 --------------------------------------------------
__global__ void k_init_hidden(const int* __restrict__ skill,
                              const int* __restrict__ label,
                              const float* __restrict__ emb,
                              float* __restrict__ hid) {
    int b = blockIdx.x;
    int n = blockIdx.y * 4 + (threadIdx.x >> 6);
    int e = threadIdx.x & 63;
    float v = 0.0f;
#pragma unroll
    for (int l = LL - 1; l >= 0; --l) {
        if (skill[b * TT + l] == n) {
            float lp = (label[b * TT + l] == 0) ? -1.0f : 1.0f;
            v = emb[n * EE + e] * lp;
            break;
        }
    }
    hid[(b * NN + n) * EE + e] = v;
}

// ---------------- exp(-dtw) ------------------------------------------------
__global__ void k_ew(const int* __restrict__ timeq) {
    int idx = blockIdx.x * blockDim.x + threadIdx.x;
    if (idx >= STEPS * BS * LL) return;
    int l = idx % LL;
    int b = (idx / LL) % BS;
    int t = idx / (LL * BS);
    float d = fabsf((float)timeq[b * TT + t + l] - (float)timeq[b * TT + t + LL]) + 1e-6f;
    float dtw = logf(d) / logf(5.0f);
    g_ew[idx] = expf(-dtw);
}

// ---------------- S rows: adj + adj@adj/N, only the 19 needed rows ---------
__global__ void k_S(const int* __restrict__ skill, const float* __restrict__ adj) {
    int chunk = blockIdx.x, k = blockIdx.y, b = blockIdx.z;
    int n = chunk * 128 + threadIdx.x;

    __shared__ float arows[NROWS][NN];
    __shared__ int rowskill[NROWS];
    if (threadIdx.x < NROWS) rowskill[threadIdx.x] = skill[b * TT + threadIdx.x];
    __syncthreads();

    const float* A = adj + ((size_t)k * BS + b) * NN * NN;
    for (int idx = threadIdx.x; idx < NROWS * NN; idx += 128) {
        int r = idx >> 9;
        int j = idx & 511;
        arows[r][j] = A[rowskill[r] * NN + j];
    }
    __syncthreads();

    float acc[NROWS];
#pragma unroll
    for (int r = 0; r < NROWS; r++) acc[r] = 0.0f;

#pragma unroll 4
    for (int j = 0; j < NN; j++) {
        float c = A[j * NN + n];
#pragma unroll
        for (int r = 0; r < NROWS; r++) acc[r] += arows[r][j] * c;
    }

    const float inv = 1.0f / (float)NN;
#pragma unroll
    for (int r = 0; r < NROWS; r++) {
        g_S[(((size_t)b * 2 + k) * NROWS + r) * NN + n] = arows[r][n] + acc[r] * inv;
    }
}

// ---------------- f-network at target node (one warp) ----------------------
__device__ __forceinline__ void fnet_warp(
    float x0, float x1, int lane, float* sx,
    const float* __restrict__ fw1, const float* __restrict__ fb1,
    const float* __restrict__ ln1g, const float* __restrict__ ln1b,
    const float* __restrict__ fw2, const float* __restrict__ fb2,
    const float* __restrict__ ln2g, const float* __restrict__ ln2b,
    const float* __restrict__ fw3, const float* __restrict__ fb3,
    float* __restrict__ outp) {

    __syncwarp();
    sx[lane] = x0; sx[lane + 32] = x1;
    __syncwarp();
    float t0 = fb1[lane], t1 = fb1[lane + 32];
#pragma unroll 8
    for (int f = 0; f < 64; f++) {
        float v = sx[f];
        t0 += v * fw1[lane * 64 + f];
        t1 += v * fw1[(lane + 32) * 64 + f];
    }
    float h0 = x0 + (t0 > 0.0f ? t0 : 0.01f * t0);
    float h1 = x1 + (t1 > 0.0f ? t1 : 0.01f * t1);

    float m = warp_sum(h0 + h1) * (1.0f / 64.0f);
    float d0 = h0 - m, d1 = h1 - m;
    float var = warp_sum(d0 * d0 + d1 * d1) * (1.0f / 64.0f);
    float r = rsqrtf(var + 1e-5f);
    float y0 = d0 * r * ln1g[lane] + ln1b[lane];
    float y1 = d1 * r * ln1g[lane + 32] + ln1b[lane + 32];

    __syncwarp();
    sx[lane] = y0; sx[lane + 32] = y1;
    __syncwarp();
    t0 = fb2[lane]; t1 = fb2[lane + 32];
#pragma unroll 8
    for (int f = 0; f < 64; f++) {
        float v = sx[f];
        t0 += v * fw2[lane * 64 + f];
        t1 += v * fw2[(lane + 32) * 64 + f];
    }
    h0 += (t0 > 0.0f ? t0 : 0.01f * t0);
    h1 += (t1 > 0.0f ? t1 : 0.01f * t1);

    m = warp_sum(h0 + h1) * (1.0f / 64.0f);
    d0 = h0 - m; d1 = h1 - m;
    var = warp_sum(d0 * d0 + d1 * d1) * (1.0f / 64.0f);
    r = rsqrtf(var + 1e-5f);
    float z0 = d0 * r * ln2g[lane] + ln2b[lane];
    float z1 = d1 * r * ln2g[lane + 32] + ln2b[lane + 32];

    float l0 = warp_sum(z0 * fw3[lane] + z1 * fw3[lane + 32]);
    float l1 = warp_sum(z0 * fw3[64 + lane] + z1 * fw3[64 + lane + 32]);
    if (lane == 0) {
        l0 += fb3[0]; l1 += fb3[1];
        *outp = 1.0f / (1.0f + expf(l0 - l1));
    }
    __syncwarp();
}

// ---------------- fused step kernel ----------------------------------------
// grid (16, BS), block 512 = 16 warps, each warp 2 nodes.
// All gmem reads issued before the staging barrier; main loop is gmem-free.
// smem (floats):
//   sW1b 4352 | sW2 4352 | sM1 16*512 | sA 512 | sHH 16*64 | sHX 16*64 |
//   sS 16*32 | sB2 64 | sEW 8 | sSH 8   = 20048 fl = 80192 B -> 2 blocks/SM
#define SW_STRIDE 68
#define SMEM_FLOATS 20048
#define SMEM_BYTES  (SMEM_FLOATS * 4)

__global__ __launch_bounds__(512, 2) void k_step(
    const float* __restrict__ hcur, float* __restrict__ hnext, int t,
    const int* __restrict__ skill,
    const float* __restrict__ fc1w, const float* __restrict__ fc1b,
    const float* __restrict__ fc2w, const float* __restrict__ fc2b,
    const float* __restrict__ fw1, const float* __restrict__ fb1,
    const float* __restrict__ ln1g, const float* __restrict__ ln1b,
    const float* __restrict__ fw2, const float* __restrict__ fb2,
    const float* __restrict__ ln2g, const float* __restrict__ ln2b,
    const float* __restrict__ fw3, const float* __restrict__ fb3,
    float* __restrict__ out) {

    extern __shared__ float s[];
    float* sW1b = s;                   // [e][f] stride 68
    float* sW2  = s + 4352;            // [e][f] stride 68
    float* sM1  = s + 8704;            // per-warp [8 l][64 f]
    float* sA   = s + 16896;           // [8 l][64 e]
    float* sHH  = s + 17408;           // per-warp hh row (A phase)
    float* sHX  = s + 18432;           // per-warp hidden row / fnet scratch
    float* sS   = s + 19456;           // per-warp S values [2 node][2 k][8 l]
    float* sB2  = s + 19968;
    float* sEW  = s + 20032;
    int*   sSH  = (int*)(s + 20040);

    int b = blockIdx.y;
    int g = blockIdx.x;
    int tid = threadIdx.x;
    int w = tid >> 5;
    int lane = tid & 31;

    int n0 = (((g << 4) + w) << 1);      // warp's two nodes

    // ---- stage W1b, W2 via float4 (2 iters/thread) ----
#pragma unroll
    for (int idx = tid; idx < 1024; idx += 512) {
        int e = idx >> 4, c4 = (idx & 15) << 2;
        float4 v1 = *(const float4*)(fc1w + e * 128 + 64 + c4);
        *(float4*)(sW1b + e * SW_STRIDE + c4) = v1;
        float4 v2 = *(const float4*)(fc2w + e * 64 + c4);
        *(float4*)(sW2 + e * SW_STRIDE + c4) = v2;
    }
    if (tid < 64) sB2[tid] = fc2b[tid];
    if (tid < 8) {
        sEW[tid] = g_ew[(t * BS + b) * LL + tid];
        sSH[tid] = skill[b * TT + t + tid];
    }

    // ---- prefetch everything gmem (latency overlaps barrier + phase 1) ----
    // hidden rows for both nodes
    float h00 = hcur[((b << 9) + n0) * EE + lane];
    float h01 = hcur[((b << 9) + n0) * EE + lane + 32];
    float h10 = hcur[((b << 9) + n0 + 1) * EE + lane];
    float h11 = hcur[((b << 9) + n0 + 1) * EE + lane + 32];
    // S rows for both nodes: lane = node*16 + k*8 + l
    int ii = lane >> 4, kq = (lane >> 3) & 1, lq = lane & 7;
    float sv = __ldg(&g_S[(((size_t)b * 2 + kq) * NROWS + (t + lq)) * NN + (n0 + ii)]);
    // hh row for phase 1 (skill via L2, no smem dependency)
    int r = w & 7;
    int sl = __ldg(&skill[b * TT + t + r]);
    float hh0 = hcur[((b << 9) + sl) * EE + lane];
    float hh1 = hcur[((b << 9) + sl) * EE + lane + 32];
    int tgt = __ldg(&skill[b * TT + t + LL]);

    __syncthreads();

    float* mysx = sHX + w * 64;
    const unsigned long long* hvx = (const unsigned long long*)mysx;
    const ulonglong2* w1bA = (const ulonglong2*)(sW1b + lane * SW_STRIDE);
    const ulonglong2* w1bB = (const ulonglong2*)(sW1b + (lane + 32) * SW_STRIDE);
    const ulonglong2* w2A  = (const ulonglong2*)(sW2 + lane * SW_STRIDE);
    const ulonglong2* w2B  = (const ulonglong2*)(sW2 + (lane + 32) * SW_STRIDE);

    // ---- phase 1: A half-row (gmem W1a) + node-0 B-matvec, all warps busy --
    float B0c, B1c;
    {
        int e = ((w >> 3) << 5) + lane;
        sHH[w * 64 + lane]      = hh0;
        sHH[w * 64 + lane + 32] = hh1;
        sS[w * 32 + lane] = sv;
        mysx[lane]      = h00;
        mysx[lane + 32] = h01;
        __syncwarp();

        // A half-row: W1a row e read straight from gmem (one reader per row)
        const ulonglong2* wa = (const ulonglong2*)(fc1w + e * 128);
        const unsigned long long* hh = (const unsigned long long*)(sHH + w * 64);
        unsigned long long aa = 0ull;
#pragma unroll
        for (int fp = 0; fp < 16; fp++) {
            ulonglong2 q = __ldg(&wa[fp]);
            fma2(aa, hh[2 * fp], q.x);
            fma2(aa, hh[2 * fp + 1], q.y);
        }
        sA[r * 64 + e] = red2(aa) + __ldg(&fc1b[e]);

        // node-0 B-matvec
        unsigned long long bp0 = 0ull, bp1 = 0ull;
#pragma unroll
        for (int fp = 0; fp < 16; fp++) {
            ulonglong2 qa = w1bA[fp];
            ulonglong2 qb = w1bB[fp];
            unsigned long long m01 = hvx[2 * fp], m23 = hvx[2 * fp + 1];
            fma2(bp0, m01, qa.x); fma2(bp0, m23, qa.y);
            fma2(bp1, m01, qb.x); fma2(bp1, m23, qb.y);
        }
        B0c = red2(bp0);
        B1c = red2(bp1);
    }
    __syncthreads();

    float* myM1 = sM1 + w * 512;
    const ulonglong2* mv2 = (const ulonglong2*)myM1;
    float* mysS = sS + w * 32;

#pragma unroll 1
    for (int i = 0; i < 2; i++) {
        int n = n0 + i;
        float B0, B1;
        if (i == 0) {
            B0 = B0c; B1 = B1c;
        } else {
            // node-1 hidden from prefetched regs + B-matvec
            mysx[lane]      = h10;
            mysx[lane + 32] = h11;
            __syncwarp();
            unsigned long long bp0 = 0ull, bp1 = 0ull;
#pragma unroll
            for (int fp = 0; fp < 16; fp++) {
                ulonglong2 qa = w1bA[fp];
                ulonglong2 qb = w1bB[fp];
                unsigned long long m01 = hvx[2 * fp], m23 = hvx[2 * fp + 1];
                fma2(bp0, m01, qa.x); fma2(bp0, m23, qa.y);
                fma2(bp1, m01, qb.x); fma2(bp1, m23, qb.y);
            }
            B0 = red2(bp0);
            B1 = red2(bp1);
        }

        // msg1 = tanh(A + B)   (single-MUFU tanh)
#pragma unroll
        for (int l = 0; l < 8; l++) {
            myM1[l * 64 + lane]      = tanha(sA[l * 64 + lane] + B0);
            myM1[l * 64 + lane + 32] = tanha(sA[l * 64 + lane + 32] + B1);
        }
        __syncwarp();

        // fc2 for all 8 l's at once (32 packed accumulators)
        unsigned long long acc0[8], acc1[8];
#pragma unroll
        for (int l = 0; l < 8; l++) { acc0[l] = 0ull; acc1[l] = 0ull; }
#pragma unroll 4
        for (int fp = 0; fp < 16; fp++) {
            ulonglong2 qa = w2A[fp];
            ulonglong2 qb = w2B[fp];
#pragma unroll
            for (int l = 0; l < 8; l++) {
                ulonglong2 m = mv2[l * 16 + fp];
                fma2(acc0[l], m.x, qa.x); fma2(acc0[l], m.y, qa.y);
                fma2(acc1[l], m.x, qb.x); fma2(acc1[l], m.y, qb.y);
            }
        }

        // msg2 = tanh(.+b2)*ew ; agg over l with prefetched S (smem broadcast)
        float b20 = sB2[lane], b21 = sB2[lane + 32];
        float ag00 = 0, ag01 = 0, ag10 = 0, ag11 = 0;
#pragma unroll
        for (int l = 0; l < 8; l++) {
            float ewl = sEW[l];
            float m0 = tanha(red2(acc0[l]) + b20) * ewl;
            float m1 = tanha(red2(acc1[l]) + b21) * ewl;
            float w0 = mysS[i * 16 + l];
            float w1v = mysS[i * 16 + 8 + l];
            ag00 += w0 * m0;   ag01 += w0 * m1;
            ag10 += w1v * m0;  ag11 += w1v * m1;
        }

        // new_hidden = mean over k
        hnext[((b << 9) + n) * EE + lane]      = 0.5f * (ag00 + ag10);
        hnext[((b << 9) + n) * EE + lane + 32] = 0.5f * (ag01 + ag11);

        // prediction head only at the target node
        if (n == tgt) {
            fnet_warp(ag00, ag01, lane, mysx, fw1, fb1, ln1g, ln1b,
                      fw2, fb2, ln2g, ln2b, fw3, fb3,
                      &out[(t * BS + b) * 2 + 0]);
            fnet_warp(ag10, ag11, lane, mysx, fw1, fb1, ln1g, ln1b,
                      fw2, fb2, ln2g, ln2b, fw3, fb3,
                      &out[(t * BS + b) * 2 + 1]);
        }
        __syncwarp();
    }
}

// ---------------- launch ----------------------------------------------------
extern "C" void kernel_launch(void* const* d_in, const int* in_sizes, int n_in,
                              void* d_out, int out_size) {
    const int*   skill = (const int*)d_in[0];
    const int*   timeq = (const int*)d_in[1];
    const int*   label = (const int*)d_in[2];
    const float* adj   = (const float*)d_in[3];
    const float* emb   = (const float*)d_in[4];
    const float* fc1w  = (const float*)d_in[5];
    const float* fc1b  = (const float*)d_in[6];
    const float* fc2w  = (const float*)d_in[7];
    const float* fc2b  = (const float*)d_in[8];
    const float* fw1   = (const float*)d_in[9];
    const float* fb1   = (const float*)d_in[10];
    const float* ln1g  = (const float*)d_in[11];
    const float* ln1b  = (const float*)d_in[12];
    const float* fw2   = (const float*)d_in[13];
    const float* fb2   = (const float*)d_in[14];
    const float* ln2g  = (const float*)d_in[15];
    const float* ln2b  = (const float*)d_in[16];
    const float* fw3   = (const float*)d_in[17];
    const float* fb3   = (const float*)d_in[18];
    float* out = (float*)d_out;

    cudaFuncSetAttribute(k_step, cudaFuncAttributeMaxDynamicSharedMemorySize, SMEM_BYTES);

    float *hA, *hB;
    cudaGetSymbolAddress((void**)&hA, g_hA);
    cudaGetSymbolAddress((void**)&hB, g_hB);

    k_init_hidden<<<dim3(BS, NN / 4), 256>>>(skill, label, emb, hA);
    k_ew<<<3, 512>>>(timeq);
    k_S<<<dim3(4, 2, BS), 128>>>(skill, adj);

    for (int t = 0; t < STEPS; t++) {
        const float* hc = (t & 1) ? hB : hA;
        float*       hn = (t & 1) ? hA : hB;
        k_step<<<dim3(16, BS), 512, SMEM_BYTES>>>(
            hc, hn, t, skill,
            fc1w, fc1b, fc2w, fc2b,
            fw1, fb1, ln1g, ln1b, fw2, fb2, ln2g, ln2b, fw3, fb3,
            out);
    }
}

// round 13
// speedup vs baseline: 1.0064x; 1.0064x over previous
#include <cuda_runtime.h>
#include <math.h>
#include <stdint.h>

#define BS 16
#define TT 20
#define NN 512
#define EE 64
#define LL 8
#define STEPS 12
#define NROWS 19
#define GRID_X 16
#define GRID_BLOCKS (GRID_X * BS)

// ---------------- scratch (device globals; no allocation allowed) ----------
__device__ float g_S[BS * 2 * NROWS * NN];
__device__ float g_hA[BS * NN * EE];
__device__ float g_hB[BS * NN * EE];
__device__ unsigned int g_barcnt;      // zero-init; returns to 0 every barrier
__device__ unsigned int g_bargen;      // monotonically increasing generation

// ---------------- helpers --------------------------------------------------
__device__ __forceinline__ float tanha(float x) {
    float r;
    asm("tanh.approx.f32 %0, %1;" : "=f"(r) : "f"(x));
    return r;
}

__device__ __forceinline__ float warp_sum(float v) {
#pragma unroll
    for (int o = 16; o > 0; o >>= 1) v += __shfl_xor_sync(0xffffffffu, v, o);
    return v;
}

__device__ __forceinline__ void fma2(unsigned long long& d,
                                     unsigned long long a,
                                     unsigned long long b) {
    asm("fma.rn.f32x2 %0, %1, %2, %0;" : "+l"(d) : "l"(a), "l"(b));
}
__device__ __forceinline__ float red2(unsigned long long p) {
    float2 r;
    asm("mov.b64 {%0,%1}, %2;" : "=f"(r.x), "=f"(r.y) : "l"(p));
    return r.x + r.y;
}

// device-wide barrier; all GRID_BLOCKS must be co-resident (they are: 2/SM).
// __threadfence (gpu scope) both releases our gmem writes and invalidates L1D.
__device__ __forceinline__ void grid_sync() {
    __threadfence();
    __syncthreads();
    if (threadIdx.x == 0) {
        volatile unsigned int* genp = &g_bargen;
        unsigned int gen = *genp;
        if (atomicAdd(&g_barcnt, 1u) == GRID_BLOCKS - 1) {
            g_barcnt = 0;
            __threadfence();
            *genp = gen + 1u;
        } else {
            while (*genp == gen) { }
        }
        __threadfence();
    }
    __syncthreads();
}

// ---------------- S rows: adj + adj@adj/N, only the 19 needed rows ---------
__global__ void k_S(const int* __restrict__ skill, const float* __restrict__ adj) {
    int chunk = blockIdx.x, k = blockIdx.y, b = blockIdx.z;
    int n = chunk * 128 + threadIdx.x;

    __shared__ float arows[NROWS][NN];
    __shared__ int rowskill[NROWS];
    if (threadIdx.x < NROWS) rowskill[threadIdx.x] = skill[b * TT + threadIdx.x];
    __syncthreads();

    const float* A = adj + ((size_t)k * BS + b) * NN * NN;
    for (int idx = threadIdx.x; idx < NROWS * NN; idx += 128) {
        int r = idx >> 9;
        int j = idx & 511;
        arows[r][j] = A[rowskill[r] * NN + j];
    }
    __syncthreads();

    float acc[NROWS];
#pragma unroll
    for (int r = 0; r < NROWS; r++) acc[r] = 0.0f;

#pragma unroll 4
    for (int j = 0; j < NN; j++) {
        float c = A[j * NN + n];
#pragma unroll
        for (int r = 0; r < NROWS; r++) acc[r] += arows[r][j] * c;
    }

    const float inv = 1.0f / (float)NN;
#pragma unroll
    for (int r = 0; r < NROWS; r++) {
        g_S[(((size_t)b * 2 + k) * NROWS + r) * NN + n] = arows[r][n] + acc[r] * inv;
    }
}

// ---------------- f-network at target node (one warp) ----------------------
__device__ __forceinline__ void fnet_warp(
    float x0, float x1, int lane, float* sx,
    const float* __restrict__ fw1, const float* __restrict__ fb1,
    const float* __restrict__ ln1g, const float* __restrict__ ln1b,
    const float* __restrict__ fw2, const float* __restrict__ fb2,
    const float* __restrict__ ln2g, const float* __restrict__ ln2b,
    const float* __restrict__ fw3, const float* __restrict__ fb3,
    float* __restrict__ outp) {

    __syncwarp();
    sx[lane] = x0; sx[lane + 32] = x1;
    __syncwarp();
    float t0 = fb1[lane], t1 = fb1[lane + 32];
#pragma unroll 8
    for (int f = 0; f < 64; f++) {
        float v = sx[f];
        t0 += v * fw1[lane * 64 + f];
        t1 += v * fw1[(lane + 32) * 64 + f];
    }
    float h0 = x0 + (t0 > 0.0f ? t0 : 0.01f * t0);
    float h1 = x1 + (t1 > 0.0f ? t1 : 0.01f * t1);

    float m = warp_sum(h0 + h1) * (1.0f / 64.0f);
    float d0 = h0 - m, d1 = h1 - m;
    float var = warp_sum(d0 * d0 + d1 * d1) * (1.0f / 64.0f);
    float r = rsqrtf(var + 1e-5f);
    float y0 = d0 * r * ln1g[lane] + ln1b[lane];
    float y1 = d1 * r * ln1g[lane + 32] + ln1b[lane + 32];

    __syncwarp();
    sx[lane] = y0; sx[lane + 32] = y1;
    __syncwarp();
    t0 = fb2[lane]; t1 = fb2[lane + 32];
#pragma unroll 8
    for (int f = 0; f < 64; f++) {
        float v = sx[f];
        t0 += v * fw2[lane * 64 + f];
        t1 += v * fw2[(lane + 32) * 64 + f];
    }
    h0 += (t0 > 0.0f ? t0 : 0.01f * t0);
    h1 += (t1 > 0.0f ? t1 : 0.01f * t1);

    m = warp_sum(h0 + h1) * (1.0f / 64.0f);
    d0 = h0 - m; d1 = h1 - m;
    var = warp_sum(d0 * d0 + d1 * d1) * (1.0f / 64.0f);
    r = rsqrtf(var + 1e-5f);
    float z0 = d0 * r * ln2g[lane] + ln2b[lane];
    float z1 = d1 * r * ln2g[lane + 32] + ln2b[lane + 32];

    float l0 = warp_sum(z0 * fw3[lane] + z1 * fw3[lane + 32]);
    float l1 = warp_sum(z0 * fw3[64 + lane] + z1 * fw3[64 + lane + 32]);
    if (lane == 0) {
        l0 += fb3[0]; l1 += fb3[1];
        *outp = 1.0f / (1.0f + expf(l0 - l1));
    }
    __syncwarp();
}

// ---------------- persistent fused kernel: all 12 steps ---------------------
// grid (16, BS), block 512 = 16 warps, each warp 2 nodes.
// smem (floats):
//   sW1b 4352 | sW2 4352 | sM1 8192 | sA 512 | sHH 1024 | sHX 1024 |
//   sS 512 | sB2 64 | sEW 96 | sSH 20   = 20148 fl = 80592 B -> 2 blocks/SM
#define SW_STRIDE 68
#define SMEM_FLOATS 20148
#define SMEM_BYTES  (SMEM_FLOATS * 4)

__global__ __launch_bounds__(512, 2) void k_main(
    const int* __restrict__ skill, const int* __restrict__ timeq,
    const int* __restrict__ label, const float* __restrict__ emb,
    const float* __restrict__ fc1w, const float* __restrict__ fc1b,
    const float* __restrict__ fc2w, const float* __restrict__ fc2b,
    const float* __restrict__ fw1, const float* __restrict__ fb1,
    const float* __restrict__ ln1g, const float* __restrict__ ln1b,
    const float* __restrict__ fw2, const float* __restrict__ fb2,
    const float* __restrict__ ln2g, const float* __restrict__ ln2b,
    const float* __restrict__ fw3, const float* __restrict__ fb3,
    float* __restrict__ out) {

    extern __shared__ float s[];
    float* sW1b = s;                   // [e][f] stride 68
    float* sW2  = s + 4352;            // [e][f] stride 68
    float* sM1  = s + 8704;            // per-warp [8 l][64 f]
    float* sA   = s + 16896;           // [8 l][64 e]
    float* sHH  = s + 17408;           // per-warp hh row (A phase)
    float* sHX  = s + 18432;           // per-warp hidden row / fnet scratch
    float* sS   = s + 19456;           // per-warp S values [2 node][2 k][8 l]
    float* sB2  = s + 19968;
    float* sEW  = s + 20032;           // [12 t][8 l] for this b
    int*   sSH  = (int*)(s + 20128);   // skill[b][0..19]

    int b = blockIdx.y;
    int g = blockIdx.x;
    int tid = threadIdx.x;
    int w = tid >> 5;
    int lane = tid & 31;
    int n0 = (((g << 4) + w) << 1);    // warp's two nodes

    // ---- one-time staging ----
#pragma unroll
    for (int idx = tid; idx < 1024; idx += 512) {
        int e = idx >> 4, c4 = (idx & 15) << 2;
        float4 v1 = *(const float4*)(fc1w + e * 128 + 64 + c4);
        *(float4*)(sW1b + e * SW_STRIDE + c4) = v1;
        float4 v2 = *(const float4*)(fc2w + e * 64 + c4);
        *(float4*)(sW2 + e * SW_STRIDE + c4) = v2;
    }
    if (tid < 64) sB2[tid] = fc2b[tid];
    if (tid < TT) sSH[tid] = skill[b * TT + tid];
    if (tid < STEPS * LL) {           // ew for all steps of this b
        int tt = tid >> 3, l = tid & 7;
        float d = fabsf((float)timeq[b * TT + tt + l]
                      - (float)timeq[b * TT + tt + LL]) + 1e-6f;
        sEW[tid] = expf(-logf(d) / logf(5.0f));
    }
    __syncthreads();

    // ---- hidden0 for this block's 32 nodes (into g_hA) ----
#pragma unroll
    for (int i = 0; i < 2; i++) {
        int n = n0 + i;
        float v0 = 0.0f, v1 = 0.0f;
#pragma unroll
        for (int l = LL - 1; l >= 0; --l) {
            if (sSH[l] == n) {
                float lp = (__ldg(&label[b * TT + l]) == 0) ? -1.0f : 1.0f;
                v0 = __ldg(&emb[n * EE + lane]) * lp;
                v1 = __ldg(&emb[n * EE + lane + 32]) * lp;
                break;
            }
        }
        g_hA[((b << 9) + n) * EE + lane]      = v0;
        g_hA[((b << 9) + n) * EE + lane + 32] = v1;
    }

    float* mysx = sHX + w * 64;
    const unsigned long long* hvx = (const unsigned long long*)mysx;
    const ulonglong2* w1bA = (const ulonglong2*)(sW1b + lane * SW_STRIDE);
    const ulonglong2* w1bB = (const ulonglong2*)(sW1b + (lane + 32) * SW_STRIDE);
    const ulonglong2* w2A  = (const ulonglong2*)(sW2 + lane * SW_STRIDE);
    const ulonglong2* w2B  = (const ulonglong2*)(sW2 + (lane + 32) * SW_STRIDE);
    float* myM1 = sM1 + w * 512;
    const ulonglong2* mv2 = (const ulonglong2*)myM1;
    float* mysS = sS + w * 32;
    int r = w & 7;
    int eA = ((w >> 3) << 5) + lane;   // this warp's A-column
    // decode for S prefetch: lane = node*16 + k*8 + l
    int ii = lane >> 4, kq = (lane >> 3) & 1, lq = lane & 7;

#pragma unroll 1
    for (int t = 0; t < STEPS; t++) {
        const float* hcur = (t & 1) ? g_hB : g_hA;
        float*       hnext = (t & 1) ? g_hA : g_hB;

        grid_sync();   // makes previous step's hnext (or hidden0) visible

        // ---- prefetch gmem (L2 via __ldcg for ping-pong buffers) ----
        float h00 = __ldcg(&hcur[((b << 9) + n0) * EE + lane]);
        float h01 = __ldcg(&hcur[((b << 9) + n0) * EE + lane + 32]);
        float h10 = __ldcg(&hcur[((b << 9) + n0 + 1) * EE + lane]);
        float h11 = __ldcg(&hcur[((b << 9) + n0 + 1) * EE + lane + 32]);
        float sv = __ldg(&g_S[(((size_t)b * 2 + kq) * NROWS + (t + lq)) * NN + (n0 + ii)]);
        int sl = sSH[t + r];
        float hh0 = __ldcg(&hcur[((b << 9) + sl) * EE + lane]);
        float hh1 = __ldcg(&hcur[((b << 9) + sl) * EE + lane + 32]);
        int tgt = sSH[t + LL];
        const float* ewt = sEW + t * LL;

        // ---- phase 1: A half-row (W1a from gmem/L1) + node-0 B-matvec ----
        float B0c, B1c;
        {
            sHH[w * 64 + lane]      = hh0;
            sHH[w * 64 + lane + 32] = hh1;
            sS[w * 32 + lane] = sv;
            mysx[lane]      = h00;
            mysx[lane + 32] = h01;
            __syncwarp();

            const ulonglong2* wa = (const ulonglong2*)(fc1w + eA * 128);
            const unsigned long long* hh = (const unsigned long long*)(sHH + w * 64);
            unsigned long long aa = 0ull;
#pragma unroll
            for (int fp = 0; fp < 16; fp++) {
                ulonglong2 q = __ldg(&wa[fp]);
                fma2(aa, hh[2 * fp], q.x);
                fma2(aa, hh[2 * fp + 1], q.y);
            }
            sA[r * 64 + eA] = red2(aa) + __ldg(&fc1b[eA]);

            unsigned long long bp0 = 0ull, bp1 = 0ull;
#pragma unroll
            for (int fp = 0; fp < 16; fp++) {
                ulonglong2 qa = w1bA[fp];
                ulonglong2 qb = w1bB[fp];
                unsigned long long m01 = hvx[2 * fp], m23 = hvx[2 * fp + 1];
                fma2(bp0, m01, qa.x); fma2(bp0, m23, qa.y);
                fma2(bp1, m01, qb.x); fma2(bp1, m23, qb.y);
            }
            B0c = red2(bp0);
            B1c = red2(bp1);
        }
        __syncthreads();

#pragma unroll 1
        for (int i = 0; i < 2; i++) {
            int n = n0 + i;
            float B0, B1;
            if (i == 0) {
                B0 = B0c; B1 = B1c;
            } else {
                mysx[lane]      = h10;
                mysx[lane + 32] = h11;
                __syncwarp();
                unsigned long long bp0 = 0ull, bp1 = 0ull;
#pragma unroll
                for (int fp = 0; fp < 16; fp++) {
                    ulonglong2 qa = w1bA[fp];
                    ulonglong2 qb = w1bB[fp];
                    unsigned long long m01 = hvx[2 * fp], m23 = hvx[2 * fp + 1];
                    fma2(bp0, m01, qa.x); fma2(bp0, m23, qa.y);
                    fma2(bp1, m01, qb.x); fma2(bp1, m23, qb.y);
                }
                B0 = red2(bp0);
                B1 = red2(bp1);
            }

            // msg1 = tanh(A + B)
#pragma unroll
            for (int l = 0; l < 8; l++) {
                myM1[l * 64 + lane]      = tanha(sA[l * 64 + lane] + B0);
                myM1[l * 64 + lane + 32] = tanha(sA[l * 64 + lane + 32] + B1);
            }
            __syncwarp();

            // fc2 for all 8 l's (32 packed accumulators)
            unsigned long long acc0[8], acc1[8];
#pragma unroll
            for (int l = 0; l < 8; l++) { acc0[l] = 0ull; acc1[l] = 0ull; }
#pragma unroll 4
            for (int fp = 0; fp < 16; fp++) {
                ulonglong2 qa = w2A[fp];
                ulonglong2 qb = w2B[fp];
#pragma unroll
                for (int l = 0; l < 8; l++) {
                    ulonglong2 m = mv2[l * 16 + fp];
                    fma2(acc0[l], m.x, qa.x); fma2(acc0[l], m.y, qa.y);
                    fma2(acc1[l], m.x, qb.x); fma2(acc1[l], m.y, qb.y);
                }
            }

            // msg2 = tanh(.+b2)*ew ; aggregate with S
            float b20 = sB2[lane], b21 = sB2[lane + 32];
            float ag00 = 0, ag01 = 0, ag10 = 0, ag11 = 0;
#pragma unroll
            for (int l = 0; l < 8; l++) {
                float ewl = ewt[l];
                float m0 = tanha(red2(acc0[l]) + b20) * ewl;
                float m1 = tanha(red2(acc1[l]) + b21) * ewl;
                float w0 = mysS[i * 16 + l];
                float w1v = mysS[i * 16 + 8 + l];
                ag00 += w0 * m0;   ag01 += w0 * m1;
                ag10 += w1v * m0;  ag11 += w1v * m1;
            }

            hnext[((b << 9) + n) * EE + lane]      = 0.5f * (ag00 + ag10);
            hnext[((b << 9) + n) * EE + lane + 32] = 0.5f * (ag01 + ag11);

            if (n == tgt) {
                fnet_warp(ag00, ag01, lane, mysx, fw1, fb1, ln1g, ln1b,
                          fw2, fb2, ln2g, ln2b, fw3, fb3,
                          &out[(t * BS + b) * 2 + 0]);
                fnet_warp(ag10, ag11, lane, mysx, fw1, fb1, ln1g, ln1b,
                          fw2, fb2, ln2g, ln2b, fw3, fb3,
                          &out[(t * BS + b) * 2 + 1]);
            }
            __syncwarp();
        }
    }
}

// ---------------- launch ----------------------------------------------------
extern "C" void kernel_launch(void* const* d_in, const int* in_sizes, int n_in,
                              void* d_out, int out_size) {
    const int*   skill = (const int*)d_in[0];
    const int*   timeq = (const int*)d_in[1];
    const int*   label = (const int*)d_in[2];
    const float* adj   = (const float*)d_in[3];
    const float* emb   = (const float*)d_in[4];
    const float* fc1w  = (const float*)d_in[5];
    const float* fc1b  = (const float*)d_in[6];
    const float* fc2w  = (const float*)d_in[7];
    const float* fc2b  = (const float*)d_in[8];
    const float* fw1   = (const float*)d_in[9];
    const float* fb1   = (const float*)d_in[10];
    const float* ln1g  = (const float*)d_in[11];
    const float* ln1b  = (const float*)d_in[12];
    const float* fw2   = (const float*)d_in[13];
    const float* fb2   = (const float*)d_in[14];
    const float* ln2g  = (const float*)d_in[15];
    const float* ln2b  = (const float*)d_in[16];
    const float* fw3   = (const float*)d_in[17];
    const float* fb3   = (const float*)d_in[18];
    float* out = (float*)d_out;

    cudaFuncSetAttribute(k_main, cudaFuncAttributeMaxDynamicSharedMemorySize, SMEM_BYTES);

    k_S<<<dim3(4, 2, BS), 128>>>(skill, adj);
    k_main<<<dim3(GRID_X, BS), 512, SMEM_BYTES>>>(
        skill, timeq, label, emb,
        fc1w, fc1b, fc2w, fc2b,
        fw1, fb1, ln1g, ln1b, fw2, fb2, ln2g, ln2b, fw3, fb3,
        out);
}

// round 14
// speedup vs baseline: 1.1018x; 1.0947x over previous
#include <cuda_runtime.h>
#include <math.h>
#include <stdint.h>

#define BS 16
#define TT 20
#define NN 512
#define EE 64
#define LL 8
#define STEPS 12
#define NROWS 19   // rows of skill_seq used as S-row indices (0..18)

// ---------------- scratch (device globals; no allocation allowed) ----------
__device__ float g_S[BS * 2 * NROWS * NN];
__device__ float g_hA[BS * NN * EE];
__device__ float g_hB[BS * NN * EE];
__device__ float g_ew[STEPS * BS * LL];

// ---------------- helpers --------------------------------------------------
__device__ __forceinline__ float tanha(float x) {
    float r;
    asm("tanh.approx.f32 %0, %1;" : "=f"(r) : "f"(x));
    return r;
}

__device__ __forceinline__ float warp_sum(float v) {
#pragma unroll
    for (int o = 16; o > 0; o >>= 1) v += __shfl_xor_sync(0xffffffffu, v, o);
    return v;
}

__device__ __forceinline__ void fma2(unsigned long long& d,
                                     unsigned long long a,
                                     unsigned long long b) {
    asm("fma.rn.f32x2 %0, %1, %2, %0;" : "+l"(d) : "l"(a), "l"(b));
}
__device__ __forceinline__ float red2(unsigned long long p) {
    float2 r;
    asm("mov.b64 {%0,%1}, %2;" : "=f"(r.x), "=f"(r.y) : "l"(p));
    return r.x + r.y;
}
__device__ __forceinline__ uint32_t f2tf32(float v) {
    uint32_t u;
    asm("cvt.rna.tf32.f32 %0, %1;" : "=r"(u) : "f"(v));
    return u;
}
__device__ __forceinline__ void mma_tf32(float& c0, float& c1, float& c2, float& c3,
                                         uint32_t a0, uint32_t a1, uint32_t a2, uint32_t a3,
                                         uint32_t b0, uint32_t b1) {
    asm("mma.sync.aligned.m16n8k8.row.col.f32.tf32.tf32.f32 "
        "{%0,%1,%2,%3},{%4,%5,%6,%7},{%8,%9},{%0,%1,%2,%3};"
        : "+f"(c0), "+f"(c1), "+f"(c2), "+f"(c3)
        : "r"(a0), "r"(a1), "r"(a2), "r"(a3), "r"(b0), "r"(b1));
}

// ---------------- hidden0 --------------------------------------------------
__global__ void k_init_hidden(const int* __restrict__ skill,
                              const int* __restrict__ label,
                              const float* __restrict__ emb,
                              float* __restrict__ hid) {
    int b = blockIdx.x;
    int n = blockIdx.y * 4 + (threadIdx.x >> 6);
    int e = threadIdx.x & 63;
    float v = 0.0f;
#pragma unroll
    for (int l = LL - 1; l >= 0; --l) {
        if (skill[b * TT + l] == n) {
            float lp = (label[b * TT + l] == 0) ? -1.0f : 1.0f;
            v = emb[n * EE + e] * lp;
            break;
        }
    }
    hid[(b * NN + n) * EE + e] = v;
}

// ---------------- exp(-dtw) ------------------------------------------------
__global__ void k_ew(const int* __restrict__ timeq) {
    int idx = blockIdx.x * blockDim.x + threadIdx.x;
    if (idx >= STEPS * BS * LL) return;
    int l = idx % LL;
    int b = (idx / LL) % BS;
    int t = idx / (LL * BS);
    float d = fabsf((float)timeq[b * TT + t + l] - (float)timeq[b * TT + t + LL]) + 1e-6f;
    float dtw = logf(d) / logf(5.0f);
    g_ew[idx] = expf(-dtw);
}

// ---------------- S rows ----------------------------------------------------
__global__ void k_S(const int* __restrict__ skill, const float* __restrict__ adj) {
    int chunk = blockIdx.x, k = blockIdx.y, b = blockIdx.z;
    int n = chunk * 128 + threadIdx.x;

    __shared__ float arows[NROWS][NN];
    __shared__ int rowskill[NROWS];
    if (threadIdx.x < NROWS) rowskill[threadIdx.x] = skill[b * TT + threadIdx.x];
    __syncthreads();

    const float* A = adj + ((size_t)k * BS + b) * NN * NN;
    for (int idx = threadIdx.x; idx < NROWS * NN; idx += 128) {
        int r = idx >> 9;
        int j = idx & 511;
        arows[r][j] = A[rowskill[r] * NN + j];
    }
    __syncthreads();

    float acc[NROWS];
#pragma unroll
    for (int r = 0; r < NROWS; r++) acc[r] = 0.0f;

#pragma unroll 4
    for (int j = 0; j < NN; j++) {
        float c = A[j * NN + n];
#pragma unroll
        for (int r = 0; r < NROWS; r++) acc[r] += arows[r][j] * c;
    }

    const float inv = 1.0f / (float)NN;
#pragma unroll
    for (int r = 0; r < NROWS; r++) {
        g_S[(((size_t)b * 2 + k) * NROWS + r) * NN + n] = arows[r][n] + acc[r] * inv;
    }
}

// ---------------- f-network at target node (one warp) ----------------------
__device__ __forceinline__ void fnet_warp(
    float x0, float x1, int lane, float* sx,
    const float* __restrict__ fw1, const float* __restrict__ fb1,
    const float* __restrict__ ln1g, const float* __restrict__ ln1b,
    const float* __restrict__ fw2, const float* __restrict__ fb2,
    const float* __restrict__ ln2g, const float* __restrict__ ln2b,
    const float* __restrict__ fw3, const float* __restrict__ fb3,
    float* __restrict__ outp) {

    __syncwarp();
    sx[lane] = x0; sx[lane + 32] = x1;
    __syncwarp();
    float t0 = fb1[lane], t1 = fb1[lane + 32];
#pragma unroll 8
    for (int f = 0; f < 64; f++) {
        float v = sx[f];
        t0 += v * fw1[lane * 64 + f];
        t1 += v * fw1[(lane + 32) * 64 + f];
    }
    float h0 = x0 + (t0 > 0.0f ? t0 : 0.01f * t0);
    float h1 = x1 + (t1 > 0.0f ? t1 : 0.01f * t1);

    float m = warp_sum(h0 + h1) * (1.0f / 64.0f);
    float d0 = h0 - m, d1 = h1 - m;
    float var = warp_sum(d0 * d0 + d1 * d1) * (1.0f / 64.0f);
    float r = rsqrtf(var + 1e-5f);
    float y0 = d0 * r * ln1g[lane] + ln1b[lane];
    float y1 = d1 * r * ln1g[lane + 32] + ln1b[lane + 32];

    __syncwarp();
    sx[lane] = y0; sx[lane + 32] = y1;
    __syncwarp();
    t0 = fb2[lane]; t1 = fb2[lane + 32];
#pragma unroll 8
    for (int f = 0; f < 64; f++) {
        float v = sx[f];
        t0 += v * fw2[lane * 64 + f];
        t1 += v * fw2[(lane + 32) * 64 + f];
    }
    h0 += (t0 > 0.0f ? t0 : 0.01f * t0);
    h1 += (t1 > 0.0f ? t1 : 0.01f * t1);

    m = warp_sum(h0 + h1) * (1.0f / 64.0f);
    d0 = h0 - m; d1 = h1 - m;
    var = warp_sum(d0 * d0 + d1 * d1) * (1.0f / 64.0f);
    r = rsqrtf(var + 1e-5f);
    float z0 = d0 * r * ln2g[lane] + ln2b[lane];
    float z1 = d1 * r * ln2g[lane + 32] + ln2b[lane + 32];

    float l0 = warp_sum(z0 * fw3[lane] + z1 * fw3[lane + 32]);
    float l1 = warp_sum(z0 * fw3[64 + lane] + z1 * fw3[64 + lane + 32]);
    if (lane == 0) {
        l0 += fb3[0]; l1 += fb3[1];
        *outp = 1.0f / (1.0f + expf(l0 - l1));
    }
    __syncwarp();
}

// ---------------- fused step kernel (fragment-direct tf32 mma fc2) ----------
// grid (16, BS), block 512 = 16 warps, each warp 2 nodes = one m16 GEMM tile.
// mma rows: gid -> (node0, l=gid), gid+8 -> (node1, l=gid).
// A-frags computed in-register: a = tf32(tanha(sA[l][f] + B[node][f])).
// W2 staged tf32 + column-pair repacked so B-frag = one LDS.64.
// smem (floats):
//   sW1b 4352 | sW2 4352 | sM2 16*544 | sA 544 | sHH 1024 | sHX 1024 |
//   sB 16*136 | sB2 64 | sEW 8 | sSH 8  = 22256 fl = 89024 B -> 2 blocks/SM
#define SW_STRIDE 68
#define SMEM_FLOATS 22256
#define SMEM_BYTES  (SMEM_FLOATS * 4)

__global__ __launch_bounds__(512, 2) void k_step(
    const float* __restrict__ hcur, float* __restrict__ hnext, int t,
    const int* __restrict__ skill,
    const float* __restrict__ fc1w, const float* __restrict__ fc1b,
    const float* __restrict__ fc2w, const float* __restrict__ fc2b,
    const float* __restrict__ fw1, const float* __restrict__ fb1,
    const float* __restrict__ ln1g, const float* __restrict__ ln1b,
    const float* __restrict__ fw2, const float* __restrict__ fb2,
    const float* __restrict__ ln2g, const float* __restrict__ ln2b,
    const float* __restrict__ fw3, const float* __restrict__ fb3,
    float* __restrict__ out) {

    extern __shared__ float s[];
    float* sW1b = s;                    // [e][f] stride 68 (fp32)
    float* sW2  = s + 4352;             // [e][f-pair-packed] stride 68 (tf32)
    float* sM2  = s + 8704;             // per-warp [8 l][64 e] stride 68
    float* sA   = s + 17408;            // [8 l][64 f] stride 68
    float* sHH  = s + 17952;            // per-warp hh row
    float* sHX  = s + 18976;            // per-warp hidden row / fnet scratch
    float* sB   = s + 20000;            // per-warp [2 node][68] B vectors
    float* sB2  = s + 22176;
    float* sEW  = s + 22240;
    int*   sSH  = (int*)(s + 22248);

    int b = blockIdx.y;
    int g = blockIdx.x;
    int tid = threadIdx.x;
    int w = tid >> 5;
    int lane = tid & 31;
    int gid = lane >> 2;      // mma group id
    int tig = lane & 3;       // thread in group

    int n0 = (((g << 4) + w) << 1);

    // ---- stage W1b (float4) and W2 (tf32, column-pair repacked) ----
#pragma unroll
    for (int idx = tid; idx < 1024; idx += 512) {
        int e = idx >> 4, c4 = (idx & 15) << 2;
        float4 v1 = *(const float4*)(fc1w + e * 128 + 64 + c4);
        *(float4*)(sW1b + e * SW_STRIDE + c4) = v1;
    }
    for (int idx = tid; idx < 4096; idx += 512) {
        int e = idx >> 6, f = idx & 63;
        // pack (f, f+4) adjacent: pos = group*8 + (f&3)*2 + ((f>>2)&1)
        int pos = (f & ~7) + ((f & 3) << 1) + ((f >> 2) & 1);
        sW2[e * SW_STRIDE + pos] = __uint_as_float(f2tf32(fc2w[idx]));
    }
    if (tid < 64) sB2[tid] = fc2b[tid];
    if (tid < 8) {
        sEW[tid] = g_ew[(t * BS + b) * LL + tid];
        sSH[tid] = skill[b * TT + t + tid];
    }

    // ---- prefetch gmem (overlaps staging barrier + phase 1) ----
    float h00 = hcur[((b << 9) + n0) * EE + lane];
    float h01 = hcur[((b << 9) + n0) * EE + lane + 32];
    float h10 = hcur[((b << 9) + n0 + 1) * EE + lane];
    float h11 = hcur[((b << 9) + n0 + 1) * EE + lane + 32];
    int ii = lane >> 4, kq = (lane >> 3) & 1, lq = lane & 7;
    float sv = __ldg(&g_S[(((size_t)b * 2 + kq) * NROWS + (t + lq)) * NN + (n0 + ii)]);
    int r = w & 7;
    int sl = __ldg(&skill[b * TT + t + r]);
    float hh0 = hcur[((b << 9) + sl) * EE + lane];
    float hh1 = hcur[((b << 9) + sl) * EE + lane + 32];
    int tgt = __ldg(&skill[b * TT + t + LL]);

    __syncthreads();

    float* mysx = sHX + w * 64;
    float* myB  = sB + w * 136;
    float* myM2 = sM2 + w * 544;
    const unsigned long long* hvx = (const unsigned long long*)mysx;
    const ulonglong2* w1bA = (const ulonglong2*)(sW1b + lane * SW_STRIDE);
    const ulonglong2* w1bB = (const ulonglong2*)(sW1b + (lane + 32) * SW_STRIDE);

    // ---- phase 1: A half-row (W1a via gmem/L2) + BOTH nodes' B-matvecs ----
    {
        int eA = ((w >> 3) << 5) + lane;
        sHH[w * 64 + lane]      = hh0;
        sHH[w * 64 + lane + 32] = hh1;
        mysx[lane]      = h00;
        mysx[lane + 32] = h01;
        __syncwarp();

        const ulonglong2* wa = (const ulonglong2*)(fc1w + eA * 128);
        const unsigned long long* hh = (const unsigned long long*)(sHH + w * 64);
        unsigned long long aa = 0ull;
#pragma unroll
        for (int fp = 0; fp < 16; fp++) {
            ulonglong2 q = __ldg(&wa[fp]);
            fma2(aa, hh[2 * fp], q.x);
            fma2(aa, hh[2 * fp + 1], q.y);
        }
        sA[r * SW_STRIDE + eA] = red2(aa) + __ldg(&fc1b[eA]);

        // node-0 B
        unsigned long long bp0 = 0ull, bp1 = 0ull;
#pragma unroll
        for (int fp = 0; fp < 16; fp++) {
            ulonglong2 qa = w1bA[fp];
            ulonglong2 qb = w1bB[fp];
            unsigned long long m01 = hvx[2 * fp], m23 = hvx[2 * fp + 1];
            fma2(bp0, m01, qa.x); fma2(bp0, m23, qa.y);
            fma2(bp1, m01, qb.x); fma2(bp1, m23, qb.y);
        }
        myB[lane]      = red2(bp0);
        myB[lane + 32] = red2(bp1);

        // node-1 B
        __syncwarp();
        mysx[lane]      = h10;
        mysx[lane + 32] = h11;
        __syncwarp();
        bp0 = 0ull; bp1 = 0ull;
#pragma unroll
        for (int fp = 0; fp < 16; fp++) {
            ulonglong2 qa = w1bA[fp];
            ulonglong2 qb = w1bB[fp];
            unsigned long long m01 = hvx[2 * fp], m23 = hvx[2 * fp + 1];
            fma2(bp0, m01, qa.x); fma2(bp0, m23, qa.y);
            fma2(bp1, m01, qb.x); fma2(bp1, m23, qb.y);
        }
        myB[68 + lane]      = red2(bp0);
        myB[68 + lane + 32] = red2(bp1);
    }
    __syncthreads();   // sA complete (written by all warps)

    // ---- fc2 as tf32 mma, A-frags computed in-register ----
    float acc[8][4];
#pragma unroll
    for (int nt = 0; nt < 8; nt++) {
        acc[nt][0] = 0.f; acc[nt][1] = 0.f; acc[nt][2] = 0.f; acc[nt][3] = 0.f;
    }
#pragma unroll
    for (int kk = 0; kk < 8; kk++) {
        int f0 = kk * 8 + tig, f1 = f0 + 4;
        float sa0 = sA[gid * SW_STRIDE + f0];
        float sa1 = sA[gid * SW_STRIDE + f1];
        float b00 = myB[f0], b10 = myB[68 + f0];
        float b01 = myB[f1], b11 = myB[68 + f1];
        uint32_t a0 = f2tf32(tanha(sa0 + b00));   // row gid   (node0, l=gid)
        uint32_t a1 = f2tf32(tanha(sa0 + b10));   // row gid+8 (node1, l=gid)
        uint32_t a2 = f2tf32(tanha(sa1 + b01));
        uint32_t a3 = f2tf32(tanha(sa1 + b11));
        const float* w2base = sW2 + kk * 8 + (tig << 1);
#pragma unroll
        for (int nt = 0; nt < 8; nt++) {
            float2 bb = *(const float2*)(w2base + (nt * 8 + gid) * SW_STRIDE);
            mma_tf32(acc[nt][0], acc[nt][1], acc[nt][2], acc[nt][3],
                     a0, a1, a2, a3,
                     __float_as_uint(bb.x), __float_as_uint(bb.y));
        }
    }

    // ---- epilogue per node: bias -> tanha -> *ew, store, aggregate ----
    float ewl = sEW[gid];
#pragma unroll 1
    for (int i = 0; i < 2; i++) {
        int n = n0 + i;
#pragma unroll
        for (int nt = 0; nt < 8; nt++) {
            float2 b2p = *(const float2*)(sB2 + nt * 8 + (tig << 1));
            float c0 = (i == 0) ? acc[nt][0] : acc[nt][2];
            float c1 = (i == 0) ? acc[nt][1] : acc[nt][3];
            float2 m;
            m.x = tanha(c0 + b2p.x) * ewl;
            m.y = tanha(c1 + b2p.y) * ewl;
            *(float2*)(myM2 + gid * SW_STRIDE + nt * 8 + (tig << 1)) = m;
        }
        __syncwarp();

        // aggregate over l with S weights (per-lane e, broadcast-free reads)
        float ag00 = 0, ag01 = 0, ag10 = 0, ag11 = 0;
        float* mysS = sB;   // reuse? no — S kept in registers below
        (void)mysS;
        {
            // wr values live in the warp's sS slot written at... -> use sv relay
        }
        // S weights: re-read from prefetched lane value via shfl-free smem:
        // stored below at first use; instead read directly from g_S via L1 (hot)
        float wr0[8], wr1[8];
#pragma unroll
        for (int l = 0; l < 8; l++) {
            wr0[l] = __ldg(&g_S[(((size_t)b * 2 + 0) * NROWS + (t + l)) * NN + n]);
            wr1[l] = __ldg(&g_S[(((size_t)b * 2 + 1) * NROWS + (t + l)) * NN + n]);
        }
#pragma unroll
        for (int l = 0; l < 8; l++) {
            float m0 = myM2[l * SW_STRIDE + lane];
            float m1 = myM2[l * SW_STRIDE + lane + 32];
            ag00 += wr0[l] * m0;  ag01 += wr0[l] * m1;
            ag10 += wr1[l] * m0;  ag11 += wr1[l] * m1;
        }

        hnext[((b << 9) + n) * EE + lane]      = 0.5f * (ag00 + ag10);
        hnext[((b << 9) + n) * EE + lane + 32] = 0.5f * (ag01 + ag11);

        if (n == tgt) {
            fnet_warp(ag00, ag01, lane, mysx, fw1, fb1, ln1g, ln1b,
                      fw2, fb2, ln2g, ln2b, fw3, fb3,
                      &out[(t * BS + b) * 2 + 0]);
            fnet_warp(ag10, ag11, lane, mysx, fw1, fb1, ln1g, ln1b,
                      fw2, fb2, ln2g, ln2b, fw3, fb3,
                      &out[(t * BS + b) * 2 + 1]);
        }
        __syncwarp();
    }
    (void)sv; (void)ii; (void)kq; (void)lq;
}

// ---------------- launch ----------------------------------------------------
extern "C" void kernel_launch(void* const* d_in, const int* in_sizes, int n_in,
                              void* d_out, int out_size) {
    const int*   skill = (const int*)d_in[0];
    const int*   timeq = (const int*)d_in[1];
    const int*   label = (const int*)d_in[2];
    const float* adj   = (const float*)d_in[3];
    const float* emb   = (const float*)d_in[4];
    const float* fc1w  = (const float*)d_in[5];
    const float* fc1b  = (const float*)d_in[6];
    const float* fc2w  = (const float*)d_in[7];
    const float* fc2b  = (const float*)d_in[8];
    const float* fw1   = (const float*)d_in[9];
    const float* fb1   = (const float*)d_in[10];
    const float* ln1g  = (const float*)d_in[11];
    const float* ln1b  = (const float*)d_in[12];
    const float* fw2   = (const float*)d_in[13];
    const float* fb2   = (const float*)d_in[14];
    const float* ln2g  = (const float*)d_in[15];
    const float* ln2b  = (const float*)d_in[16];
    const float* fw3   = (const float*)d_in[17];
    const float* fb3   = (const float*)d_in[18];
    float* out = (float*)d_out;

    cudaFuncSetAttribute(k_step, cudaFuncAttributeMaxDynamicSharedMemorySize, SMEM_BYTES);

    float *hA, *hB;
    cudaGetSymbolAddress((void**)&hA, g_hA);
    cudaGetSymbolAddress((void**)&hB, g_hB);

    k_init_hidden<<<dim3(BS, NN / 4), 256>>>(skill, label, emb, hA);
    k_ew<<<3, 512>>>(timeq);
    k_S<<<dim3(4, 2, BS), 128>>>(skill, adj);

    for (int t = 0; t < STEPS; t++) {
        const float* hc = (t & 1) ? hB : hA;
        float*       hn = (t & 1) ? hA : hB;
        k_step<<<dim3(16, BS), 512, SMEM_BYTES>>>(
            hc, hn, t, skill,
            fc1w, fc1b, fc2w, fc2b,
            fw1, fb1, ln1g, ln1b, fw2, fb2, ln2g, ln2b, fw3, fb3,
            out);
    }
}